// round 5
// baseline (speedup 1.0000x reference)
#include <cuda_runtime.h>
#include <math.h>

#define S_LEN 256
#define DM 512      // d_model
#define DR 512      // d_rnn
#define Y_ELEMS ((size_t)S_LEN * DR * DM)

// Scratch for gate coefficients (device globals: no allocation allowed)
__device__ float g_a[S_LEN * DR];
__device__ float g_c[S_LEN * DR];

// ---------------- f32x2 packed-FMA helpers (sm_103a) ----------------
__device__ __forceinline__ unsigned long long pack2(float lo, float hi) {
    unsigned long long r;
    unsigned int a = __float_as_uint(lo), b = __float_as_uint(hi);
    asm("mov.b64 %0, {%1, %2};" : "=l"(r) : "r"(a), "r"(b));
    return r;
}
__device__ __forceinline__ void unpack2(unsigned long long v, float &lo, float &hi) {
    unsigned int a, b;
    asm("mov.b64 {%0, %1}, %2;" : "=r"(a), "=r"(b) : "l"(v));
    lo = __uint_as_float(a);
    hi = __uint_as_float(b);
}
__device__ __forceinline__ void fma2(unsigned long long &d, unsigned long long a,
                                     unsigned long long b) {
    asm("fma.rn.f32x2 %0, %1, %2, %0;" : "+l"(d) : "l"(a), "l"(b));
}
// Streaming 128-bit store (evict-first: keep L2 clean for the x working set)
__device__ __forceinline__ void stcs4(float *p, float4 v) {
    asm volatile("st.global.cs.v4.f32 [%0], {%1, %2, %3, %4};"
                 :: "l"(p), "f"(v.x), "f"(v.y), "f"(v.z), "f"(v.w) : "memory");
}

// ---------------- Kernel A: gate GEMM + nonlinearity ----------------
// z[t, j]      = sum_k x[t,k] * W1[j,k]
// inp = sigmoid(z[:, i]), rec = sigmoid(z[:, i+512])
// a = exp(-8 * softplus(Lambda_i) * rec); c = sqrt(1 - a*a) * inp
//
// Tile: 16 t-rows x (64 j + the matching 64 j+512), Ktile = 32, 256 threads.
// Each thread: 1 t-row x 4 j per half -> 2 f32x2 accumulators per half.
#define MT 16
#define NT 64
#define KT 32

__global__ __launch_bounds__(256) void gate_gemm_kernel(
    const float *__restrict__ x, const float *__restrict__ W1,
    const float *__restrict__ b1, const float *__restrict__ Lam) {
    __shared__ float As[KT][MT + 1];      // [k][t], padded for conflict-free store
    __shared__ float Bs0[KT][NT + 4];     // [k][j],   j half (stride 68: 16B-aligned rows)
    __shared__ float Bs1[KT][NT + 4];     // [k][j+512]

    const int tid = threadIdx.x;
    const int t0 = blockIdx.y * MT;       // 16 t-tiles
    const int j0 = blockIdx.x * NT;       // 8 j-tiles over [0,512)

    const int mi = tid >> 4;              // 0..15 (t-row)
    const int n0 = (tid & 15) * 4;        // 0..60 (j quad)

    unsigned long long acc0[2] = {0ull, 0ull};
    unsigned long long acc1[2] = {0ull, 0ull};

    // load mappings
    const int la_t = tid >> 4;            // 16 t x 32 k, 2 floats/thread
    const int la_k = (tid & 15) * 2;
    const int lb_j = tid >> 2;            // 64 j x 32 k, 8 floats/thread
    const int lb_k = (tid & 3) * 8;

    for (int k0 = 0; k0 < DM; k0 += KT) {
        float2 av = *(const float2 *)&x[(t0 + la_t) * DM + k0 + la_k];
        const float *wr0 = &W1[(size_t)(j0 + lb_j) * DM + k0 + lb_k];
        const float *wr1 = &W1[(size_t)(j0 + 512 + lb_j) * DM + k0 + lb_k];
        float4 b0a = *(const float4 *)wr0;
        float4 b0b = *(const float4 *)(wr0 + 4);
        float4 b1a = *(const float4 *)wr1;
        float4 b1b = *(const float4 *)(wr1 + 4);

        __syncthreads();   // previous tile fully consumed
        As[la_k][la_t] = av.x;
        As[la_k + 1][la_t] = av.y;
        Bs0[lb_k + 0][lb_j] = b0a.x; Bs0[lb_k + 1][lb_j] = b0a.y;
        Bs0[lb_k + 2][lb_j] = b0a.z; Bs0[lb_k + 3][lb_j] = b0a.w;
        Bs0[lb_k + 4][lb_j] = b0b.x; Bs0[lb_k + 5][lb_j] = b0b.y;
        Bs0[lb_k + 6][lb_j] = b0b.z; Bs0[lb_k + 7][lb_j] = b0b.w;
        Bs1[lb_k + 0][lb_j] = b1a.x; Bs1[lb_k + 1][lb_j] = b1a.y;
        Bs1[lb_k + 2][lb_j] = b1a.z; Bs1[lb_k + 3][lb_j] = b1a.w;
        Bs1[lb_k + 4][lb_j] = b1b.x; Bs1[lb_k + 5][lb_j] = b1b.y;
        Bs1[lb_k + 6][lb_j] = b1b.z; Bs1[lb_k + 7][lb_j] = b1b.w;
        __syncthreads();

#pragma unroll
        for (int k = 0; k < KT; k++) {
            float a = As[k][mi];
            unsigned long long ad = pack2(a, a);
            const unsigned long long *bp0 = (const unsigned long long *)&Bs0[k][n0];
            const unsigned long long *bp1 = (const unsigned long long *)&Bs1[k][n0];
            fma2(acc0[0], ad, bp0[0]);
            fma2(acc0[1], ad, bp0[1]);
            fma2(acc1[0], ad, bp1[0]);
            fma2(acc1[1], ad, bp1[1]);
        }
    }

    // Epilogue: bias + sigmoid + gates
    float o0[4], o1[4];
    unpack2(acc0[0], o0[0], o0[1]);
    unpack2(acc0[1], o0[2], o0[3]);
    unpack2(acc1[0], o1[0], o1[1]);
    unpack2(acc1[1], o1[2], o1[3]);

    const int t = t0 + mi;
#pragma unroll
    for (int q = 0; q < 4; q++) {
        int i = j0 + n0 + q;                               // gate channel in [0,512)
        float inp = 1.0f / (1.0f + expf(-(o0[q] + b1[i])));
        float rec = 1.0f / (1.0f + expf(-(o1[q] + b1[i + 512])));
        float sp = log1pf(expf(Lam[i]));                   // softplus(Lambda)
        float a = expf(-8.0f * sp * rec);
        float c = sqrtf(fmaxf(1.0f - a * a, 0.0f)) * inp;
        g_a[t * DR + i] = a;
        g_c[t * DR + i] = c;
    }
}

// ---------------- Kernel B: linear recurrence scan ----------------
// h[i,d] = a[t,i]*h[i,d] + c[t,i]*x[t,d];  y[t,i,d] = h[i,d]
// Block: 4 i-channels x all 512 d. 256 threads (8 warps), each thread owns
// 2 channels x 1 float4 of d. G=4 keeps x L2 read traffic at 64 MB.
__global__ __launch_bounds__(256) void scan_kernel(
    const float *__restrict__ x, const float *__restrict__ state0,
    float *__restrict__ out) {
    __shared__ float sa[S_LEN][4];
    __shared__ float sc[S_LEN][4];

    const int tid = threadIdx.x;          // 0..255
    const int i0 = blockIdx.x * 4;        // 4 channels per block
    const int d0 = (tid & 127) * 4;       // d quad
    const int ch = (tid >> 7) * 2;        // 0 or 2: this thread's channel pair

    // stage gate coefficients for this block's 4 channels
    for (int r = tid; r < S_LEN; r += 256) {
        *(float4 *)&sa[r][0] = *(const float4 *)&g_a[r * DR + i0];
        *(float4 *)&sc[r][0] = *(const float4 *)&g_c[r * DR + i0];
    }

    float4 h[2];
#pragma unroll
    for (int ii = 0; ii < 2; ii++)
        h[ii] = *(const float4 *)&state0[(size_t)(i0 + ch + ii) * DM + d0];
    __syncthreads();

    float *__restrict__ y = out;
    float *__restrict__ st = out + Y_ELEMS;

#pragma unroll 4
    for (int t = 0; t < S_LEN; t++) {
        float4 xv = *(const float4 *)&x[t * DM + d0];
#pragma unroll
        for (int ii = 0; ii < 2; ii++) {
            float a = sa[t][ch + ii];
            float c = sc[t][ch + ii];
            h[ii].x = fmaf(a, h[ii].x, c * xv.x);
            h[ii].y = fmaf(a, h[ii].y, c * xv.y);
            h[ii].z = fmaf(a, h[ii].z, c * xv.z);
            h[ii].w = fmaf(a, h[ii].w, c * xv.w);
            stcs4(&y[((size_t)t * DR + (i0 + ch + ii)) * DM + d0], h[ii]);
        }
    }
#pragma unroll
    for (int ii = 0; ii < 2; ii++)
        *(float4 *)&st[(size_t)(i0 + ch + ii) * DM + d0] = h[ii];
}

// ---------------- launch ----------------
extern "C" void kernel_launch(void *const *d_in, const int *in_sizes, int n_in,
                              void *d_out, int out_size) {
    const float *x = (const float *)d_in[0];      // (256, 512)
    const float *state = (const float *)d_in[1];  // (512, 512)
    const float *W1 = (const float *)d_in[2];     // (1024, 512)
    const float *b1 = (const float *)d_in[3];     // (1024,)
    const float *Lam = (const float *)d_in[4];    // (512,)
    float *out = (float *)d_out;                  // y (256,512,512) then state (512,512)

    dim3 gridA(DR / NT, S_LEN / MT);              // 8 x 16 = 128 blocks
    gate_gemm_kernel<<<gridA, 256>>>(x, W1, b1, Lam);
    scan_kernel<<<DR / 4, 256>>>(x, state, out);
}

// round 16
// speedup vs baseline: 1.0266x; 1.0266x over previous
#include <cuda_runtime.h>
#include <math.h>

#define S_LEN 256
#define DM 512      // d_model
#define DR 512      // d_rnn
#define Y_ELEMS ((size_t)S_LEN * DR * DM)

// Scratch for gate coefficients (device globals: no allocation allowed)
__device__ float g_a[S_LEN * DR];
__device__ float g_c[S_LEN * DR];

// ---------------- f32x2 packed-FMA helpers (sm_103a) ----------------
__device__ __forceinline__ unsigned long long pack2(float lo, float hi) {
    unsigned long long r;
    unsigned int a = __float_as_uint(lo), b = __float_as_uint(hi);
    asm("mov.b64 %0, {%1, %2};" : "=l"(r) : "r"(a), "r"(b));
    return r;
}
__device__ __forceinline__ void unpack2(unsigned long long v, float &lo, float &hi) {
    unsigned int a, b;
    asm("mov.b64 {%0, %1}, %2;" : "=r"(a), "=r"(b) : "l"(v));
    lo = __uint_as_float(a);
    hi = __uint_as_float(b);
}
__device__ __forceinline__ void fma2(unsigned long long &d, unsigned long long a,
                                     unsigned long long b) {
    asm("fma.rn.f32x2 %0, %1, %2, %0;" : "+l"(d) : "l"(a), "l"(b));
}
__device__ __forceinline__ unsigned long long mul2(unsigned long long a,
                                                   unsigned long long b) {
    unsigned long long r;
    asm("mul.rn.f32x2 %0, %1, %2;" : "=l"(r) : "l"(a), "l"(b));
    return r;
}

// ---------------- Kernel A: gate GEMM + nonlinearity ----------------
#define MT 16
#define NT 64
#define KT 32

__global__ __launch_bounds__(256) void gate_gemm_kernel(
    const float *__restrict__ x, const float *__restrict__ W1,
    const float *__restrict__ b1, const float *__restrict__ Lam) {
    __shared__ float As[KT][MT + 1];
    __shared__ float Bs0[KT][NT + 4];
    __shared__ float Bs1[KT][NT + 4];

    const int tid = threadIdx.x;
    const int t0 = blockIdx.y * MT;
    const int j0 = blockIdx.x * NT;

    const int mi = tid >> 4;
    const int n0 = (tid & 15) * 4;

    unsigned long long acc0[2] = {0ull, 0ull};
    unsigned long long acc1[2] = {0ull, 0ull};

    const int la_t = tid >> 4;
    const int la_k = (tid & 15) * 2;
    const int lb_j = tid >> 2;
    const int lb_k = (tid & 3) * 8;

    for (int k0 = 0; k0 < DM; k0 += KT) {
        float2 av = *(const float2 *)&x[(t0 + la_t) * DM + k0 + la_k];
        const float *wr0 = &W1[(size_t)(j0 + lb_j) * DM + k0 + lb_k];
        const float *wr1 = &W1[(size_t)(j0 + 512 + lb_j) * DM + k0 + lb_k];
        float4 b0a = *(const float4 *)wr0;
        float4 b0b = *(const float4 *)(wr0 + 4);
        float4 b1a = *(const float4 *)wr1;
        float4 b1b = *(const float4 *)(wr1 + 4);

        __syncthreads();
        As[la_k][la_t] = av.x;
        As[la_k + 1][la_t] = av.y;
        Bs0[lb_k + 0][lb_j] = b0a.x; Bs0[lb_k + 1][lb_j] = b0a.y;
        Bs0[lb_k + 2][lb_j] = b0a.z; Bs0[lb_k + 3][lb_j] = b0a.w;
        Bs0[lb_k + 4][lb_j] = b0b.x; Bs0[lb_k + 5][lb_j] = b0b.y;
        Bs0[lb_k + 6][lb_j] = b0b.z; Bs0[lb_k + 7][lb_j] = b0b.w;
        Bs1[lb_k + 0][lb_j] = b1a.x; Bs1[lb_k + 1][lb_j] = b1a.y;
        Bs1[lb_k + 2][lb_j] = b1a.z; Bs1[lb_k + 3][lb_j] = b1a.w;
        Bs1[lb_k + 4][lb_j] = b1b.x; Bs1[lb_k + 5][lb_j] = b1b.y;
        Bs1[lb_k + 6][lb_j] = b1b.z; Bs1[lb_k + 7][lb_j] = b1b.w;
        __syncthreads();

#pragma unroll
        for (int k = 0; k < KT; k++) {
            float a = As[k][mi];
            unsigned long long ad = pack2(a, a);
            const unsigned long long *bp0 = (const unsigned long long *)&Bs0[k][n0];
            const unsigned long long *bp1 = (const unsigned long long *)&Bs1[k][n0];
            fma2(acc0[0], ad, bp0[0]);
            fma2(acc0[1], ad, bp0[1]);
            fma2(acc1[0], ad, bp1[0]);
            fma2(acc1[1], ad, bp1[1]);
        }
    }

    float o0[4], o1[4];
    unpack2(acc0[0], o0[0], o0[1]);
    unpack2(acc0[1], o0[2], o0[3]);
    unpack2(acc1[0], o1[0], o1[1]);
    unpack2(acc1[1], o1[2], o1[3]);

    const int t = t0 + mi;
#pragma unroll
    for (int q = 0; q < 4; q++) {
        int i = j0 + n0 + q;
        float inp = 1.0f / (1.0f + expf(-(o0[q] + b1[i])));
        float rec = 1.0f / (1.0f + expf(-(o1[q] + b1[i + 512])));
        float sp = log1pf(expf(Lam[i]));
        float a = expf(-8.0f * sp * rec);
        float c = sqrtf(fmaxf(1.0f - a * a, 0.0f)) * inp;
        g_a[t * DR + i] = a;
        g_c[t * DR + i] = c;
    }
}

// ---------------- Kernel B: linear recurrence scan ----------------
// h[i,d] = a[t,i]*h[i,d] + c[t,i]*x[t,d];  y[t,i,d] = h[i,d]
// Block: 2 i-channels x full 512 d. 256 threads (8 warps), ONE channel and
// one float4 of d per thread. Grid = 256 CTAs -> ~2 CTAs/SM on 148 SMs
// (R5 ncu showed 128 CTAs left 20 SMs idle at occ=12.6%).
// G=2 doubles x L2 reads to ~134 MB; LTS total ~390 MB stays at the
// DRAM-store floor. Stores use __stcs (no compiler barrier) + explicit
// next-t prefetch so x loads batch for MLP.
__global__ __launch_bounds__(256) void scan_kernel(
    const float *__restrict__ x, const float *__restrict__ state0,
    float *__restrict__ out) {
    __shared__ unsigned long long sa2[S_LEN][2];  // [t][ch]: (a,a) packed
    __shared__ unsigned long long sc2[S_LEN][2];  // [t][ch]: (c,c) packed

    const int tid = threadIdx.x;          // 0..255
    const int i0 = blockIdx.x * 2;        // 2 channels per block
    const int d0 = (tid & 127) * 4;       // d quad
    const int ch = tid >> 7;              // 0 or 1: this thread's channel

    // stage gate coefficients, duplicated into f32x2 lanes
    for (int r = tid; r < S_LEN; r += 256) {
        float2 av = *(const float2 *)&g_a[r * DR + i0];
        float2 cv = *(const float2 *)&g_c[r * DR + i0];
        sa2[r][0] = pack2(av.x, av.x); sa2[r][1] = pack2(av.y, av.y);
        sc2[r][0] = pack2(cv.x, cv.x); sc2[r][1] = pack2(cv.y, cv.y);
    }

    unsigned long long h0, h1;
    {
        float4 hv = *(const float4 *)&state0[(size_t)(i0 + ch) * DM + d0];
        h0 = pack2(hv.x, hv.y);
        h1 = pack2(hv.z, hv.w);
    }
    __syncthreads();

    const float *xcol = x + d0;
    float *yp = out + (size_t)(i0 + ch) * DM + d0;   // this thread's channel
    float *st = out + Y_ELEMS;

    float4 xv = __ldg((const float4 *)xcol);         // prefetch t=0

#pragma unroll 8
    for (int t = 0; t < S_LEN; t++) {
        // prefetch next x (clamped; address math independent of compute)
        int tn = (t + 1 < S_LEN) ? t + 1 : t;
        float4 xnext = __ldg((const float4 *)(xcol + (size_t)tn * DM));

        unsigned long long xlo = pack2(xv.x, xv.y);
        unsigned long long xhi = pack2(xv.z, xv.w);

        unsigned long long a2 = sa2[t][ch], c2 = sc2[t][ch];
        unsigned long long lo = mul2(c2, xlo), hi = mul2(c2, xhi);
        fma2(lo, a2, h0);   // lo = a*h + c*x
        fma2(hi, a2, h1);
        h0 = lo; h1 = hi;

        float4 o;
        unpack2(lo, o.x, o.y);
        unpack2(hi, o.z, o.w);
        __stcs((float4 *)(yp + (size_t)t * (DR * DM)), o);

        xv = xnext;
    }

    {
        float4 o;
        unpack2(h0, o.x, o.y);
        unpack2(h1, o.z, o.w);
        *(float4 *)&st[(size_t)(i0 + ch) * DM + d0] = o;
    }
}

// ---------------- launch ----------------
extern "C" void kernel_launch(void *const *d_in, const int *in_sizes, int n_in,
                              void *d_out, int out_size) {
    const float *x = (const float *)d_in[0];      // (256, 512)
    const float *state = (const float *)d_in[1];  // (512, 512)
    const float *W1 = (const float *)d_in[2];     // (1024, 512)
    const float *b1 = (const float *)d_in[3];     // (1024,)
    const float *Lam = (const float *)d_in[4];    // (512,)
    float *out = (float *)d_out;                  // y (256,512,512) then state (512,512)

    dim3 gridA(DR / NT, S_LEN / MT);              // 8 x 16 = 128 blocks
    gate_gemm_kernel<<<gridA, 256>>>(x, W1, b1, Lam);
    scan_kernel<<<DR / 2, 256>>>(x, state, out);  // 256 blocks
}